// round 7
// baseline (speedup 1.0000x reference)
#include <cuda_runtime.h>
#include <cuda_fp16.h>
#include <cstdint>

#define NN 100000
#define NE 1600000
#define NG 256
#define D  128
#define DOUT 64

// ---------------- scratch (static device globals; no allocs) ----------------
__device__ __align__(16) float  g_h1[(size_t)NN * D];
__device__ __align__(16) float  g_h2[(size_t)NN * D];
__device__ __align__(16) float  g_agg[(size_t)NN * D];
__device__ __align__(16) __half g_hx[(size_t)NN * D];   // fp16 shadow of current activations
__device__ __align__(16) int    g_rowoff[NN + 1];
__device__ __align__(16) int    g_cursor[NN];
__device__ __align__(16) int    g_count[NN];
__device__ __align__(16) int    g_csr[NE];
__device__ __align__(16) float  g_deginv[NN];
__device__ __align__(16) float  g_pool[NG * 2 * D];
__device__ __align__(16) int    g_gstart[NG + 1];

// ---------------- init ----------------
__global__ void k_init() {
    int i = blockIdx.x * blockDim.x + threadIdx.x;
    if (i < NN) g_count[i] = 0;
}

// ---------------- fp16 cast of x into shadow buffer ----------------
__global__ void k_xcast(const float* __restrict__ x) {
    int i = blockIdx.x * blockDim.x + threadIdx.x;   // one float4 per thread
    if (i >= NN * D / 4) return;
    float4 v = *(const float4*)(x + (size_t)i * 4);
    __half2 h0 = __floats2half2_rn(v.x, v.y);
    __half2 h1 = __floats2half2_rn(v.z, v.w);
    uint2 pk = make_uint2(*(uint32_t*)&h0, *(uint32_t*)&h1);
    *(uint2*)(g_hx + (size_t)i * 4) = pk;
}

// ---------------- in-degree histogram over dst ----------------
__global__ void k_hist(const int* __restrict__ ei) {
    int e = blockIdx.x * blockDim.x + threadIdx.x;
    if (e < NE) {
        int d = ei[NE + e];
        atomicAdd(&g_count[d], 1);
    }
}

// ---------------- single-block exclusive scan ----------------
__global__ void k_scan() {
    const int CH = 98;
    __shared__ int sc[1024];
    int t = threadIdx.x;
    int base = t * CH;
    int s = 0;
    for (int i = 0; i < CH; i++) {
        int idx = base + i;
        if (idx < NN) s += g_count[idx];
    }
    sc[t] = s;
    __syncthreads();
    for (int off = 1; off < 1024; off <<= 1) {
        int v = (t >= off) ? sc[t - off] : 0;
        __syncthreads();
        sc[t] += v;
        __syncthreads();
    }
    int run = sc[t] - s;
    for (int i = 0; i < CH; i++) {
        int idx = base + i;
        if (idx < NN) {
            int c = g_count[idx];
            g_rowoff[idx] = run;
            g_cursor[idx] = run;
            g_deginv[idx] = 1.0f / (float)max(c, 1);
            run += c;
        }
    }
    if (t == 1023) g_rowoff[NN] = sc[1023];
}

// ---------------- CSR fill ----------------
__global__ void k_fill(const int* __restrict__ ei) {
    int e = blockIdx.x * blockDim.x + threadIdx.x;
    if (e < NE) {
        int s = ei[e];
        int d = ei[NE + e];
        int pos = atomicAdd(&g_cursor[d], 1);
        g_csr[pos] = s;
    }
}

// ---------------- graph boundaries (batch sorted) ----------------
__global__ void k_gbounds(const int* __restrict__ batch) {
    int g = threadIdx.x;
    if (g > NG) return;
    int lo = 0, hi = NN;
    while (lo < hi) {
        int mid = (lo + hi) >> 1;
        if (batch[mid] < g) lo = mid + 1; else hi = mid;
    }
    g_gstart[g] = lo;
}

// ---------------- gather-mean aggregation (fp16 rows, fp32 accum) ----------
// one warp per node; lane covers 4 features = 8 bytes of fp16.
__global__ void k_agg() {
    int node = (blockIdx.x * blockDim.x + threadIdx.x) >> 5;
    if (node >= NN) return;
    int lane = threadIdx.x & 31;
    int beg = g_rowoff[node], end = g_rowoff[node + 1];
    float4 acc = make_float4(0.f, 0.f, 0.f, 0.f);
    for (int e = beg; e < end; e++) {
        int s = g_csr[e];
        uint2 pk = *(const uint2*)(g_hx + (size_t)s * D + lane * 4);
        float2 f0 = __half22float2(*(__half2*)&pk.x);
        float2 f1 = __half22float2(*(__half2*)&pk.y);
        acc.x += f0.x; acc.y += f0.y; acc.z += f1.x; acc.w += f1.y;
    }
    float sc = g_deginv[node];
    acc.x *= sc; acc.y *= sc; acc.z *= sc; acc.w *= sc;
    *(float4*)(g_agg + (size_t)node * D + lane * 4) = acc;
}

// ---------------- tf32 round-to-nearest helper ----------------
__device__ __forceinline__ float tf32r(float x) {
    uint32_t u;
    asm("cvt.rna.tf32.f32 %0, %1;" : "=r"(u) : "f"(x));
    return __uint_as_float(u);
}

// ---------------- fused GEMM (tf32 tensor cores) ----------------
// hout = act(agg@Wrel + hin@Wroot + b); optionally writes fp16 shadow.
__global__ __launch_bounds__(256) void k_gemm(
    const float* __restrict__ A0,    // agg, k in [0,128)
    const float* __restrict__ A1,    // hin, k in [128,256)
    const float* __restrict__ Wrel,
    const float* __restrict__ Wroot,
    const float* __restrict__ bias,
    float* __restrict__ hout,
    int doRelu, int writeHalf)
{
    __shared__ float As[16][132];
    __shared__ float Bs[16][132];
    int row0 = blockIdx.x * 128;
    int tid  = threadIdx.x;
    int warp = tid >> 5, lane = tid & 31;
    int wm = warp >> 2;
    int wn = warp & 3;
    int r  = lane >> 2;
    int cq = lane & 3;

    float acc[4][4][4];
#pragma unroll
    for (int mi = 0; mi < 4; mi++)
#pragma unroll
        for (int ni = 0; ni < 4; ni++)
#pragma unroll
            for (int q = 0; q < 4; q++) acc[mi][ni][q] = 0.f;

#pragma unroll 1
    for (int kt = 0; kt < 16; kt++) {
        int k0 = kt * 16;
        const float* src = (k0 < 128) ? A0 : A1;
        const float* W   = (k0 < 128) ? Wrel : Wroot;
        int kc = k0 & 127;

#pragma unroll
        for (int i = 0; i < 2; i++) {
            int slot = tid * 2 + i;
            int rr = slot >> 2;
            int c4 = (slot & 3) * 4;
            float4 v = make_float4(0.f, 0.f, 0.f, 0.f);
            int grow = row0 + rr;
            if (grow < NN)
                v = *(const float4*)(src + (size_t)grow * D + kc + c4);
            As[c4 + 0][rr] = tf32r(v.x);
            As[c4 + 1][rr] = tf32r(v.y);
            As[c4 + 2][rr] = tf32r(v.z);
            As[c4 + 3][rr] = tf32r(v.w);
        }
#pragma unroll
        for (int i = 0; i < 2; i++) {
            int slot = tid * 2 + i;
            int kk = slot >> 5;
            int n4 = (slot & 31) * 4;
            float4 v = *(const float4*)(W + (size_t)(kc + kk) * D + n4);
            float4 cv = make_float4(tf32r(v.x), tf32r(v.y), tf32r(v.z), tf32r(v.w));
            *(float4*)(&Bs[kk][n4]) = cv;
        }
        __syncthreads();

#pragma unroll
        for (int ks = 0; ks < 16; ks += 8) {
            uint32_t bf[4][2];
#pragma unroll
            for (int ni = 0; ni < 4; ni++) {
                int n = wn * 32 + ni * 8 + r;
                bf[ni][0] = __float_as_uint(Bs[ks + cq][n]);
                bf[ni][1] = __float_as_uint(Bs[ks + cq + 4][n]);
            }
#pragma unroll
            for (int mi = 0; mi < 4; mi++) {
                int row = wm * 64 + mi * 16 + r;
                uint32_t a0 = __float_as_uint(As[ks + cq][row]);
                uint32_t a1 = __float_as_uint(As[ks + cq][row + 8]);
                uint32_t a2 = __float_as_uint(As[ks + cq + 4][row]);
                uint32_t a3 = __float_as_uint(As[ks + cq + 4][row + 8]);
#pragma unroll
                for (int ni = 0; ni < 4; ni++) {
                    asm volatile(
                        "mma.sync.aligned.m16n8k8.row.col.f32.tf32.tf32.f32 "
                        "{%0,%1,%2,%3}, {%4,%5,%6,%7}, {%8,%9}, {%0,%1,%2,%3};"
                        : "+f"(acc[mi][ni][0]), "+f"(acc[mi][ni][1]),
                          "+f"(acc[mi][ni][2]), "+f"(acc[mi][ni][3])
                        : "r"(a0), "r"(a1), "r"(a2), "r"(a3),
                          "r"(bf[ni][0]), "r"(bf[ni][1]));
                }
            }
        }
        __syncthreads();
    }

    // epilogue: bias + relu + store fp32 (+ fp16 shadow)
#pragma unroll
    for (int mi = 0; mi < 4; mi++) {
        int r0g = row0 + wm * 64 + mi * 16 + r;
        int r1g = r0g + 8;
#pragma unroll
        for (int ni = 0; ni < 4; ni++) {
            int col = wn * 32 + ni * 8 + 2 * cq;
            float bz0 = bias[col], bz1 = bias[col + 1];
            float v0 = acc[mi][ni][0] + bz0, v1 = acc[mi][ni][1] + bz1;
            float v2 = acc[mi][ni][2] + bz0, v3 = acc[mi][ni][3] + bz1;
            if (doRelu) {
                v0 = fmaxf(v0, 0.f); v1 = fmaxf(v1, 0.f);
                v2 = fmaxf(v2, 0.f); v3 = fmaxf(v3, 0.f);
            }
            if (r0g < NN) {
                *(float2*)(hout + (size_t)r0g * D + col) = make_float2(v0, v1);
                if (writeHalf) {
                    __half2 h = __floats2half2_rn(v0, v1);
                    *(uint32_t*)(g_hx + (size_t)r0g * D + col) = *(uint32_t*)&h;
                }
            }
            if (r1g < NN) {
                *(float2*)(hout + (size_t)r1g * D + col) = make_float2(v2, v3);
                if (writeHalf) {
                    __half2 h = __floats2half2_rn(v2, v3);
                    *(uint32_t*)(g_hx + (size_t)r1g * D + col) = *(uint32_t*)&h;
                }
            }
        }
    }
}

// ---------------- pooling: one block per graph over contiguous range ----
__global__ __launch_bounds__(128) void k_pool() {
    int g = blockIdx.x;
    int n = threadIdx.x;
    int beg = g_gstart[g], end = g_gstart[g + 1];
    float sa = 0.f, sh = 0.f;
    for (int node = beg; node < end; node++) {
        sa += g_agg[(size_t)node * D + n];
        sh += g_h2[(size_t)node * D + n];
    }
    int cnt = end - beg;
    float cinv = 1.0f / (float)max(cnt, 1);
    g_pool[g * 2 * D + n]     = sa * cinv;
    g_pool[g * 2 * D + D + n] = sh * cinv;
}

// ---------------- final head: layer3 (pooled) + linear, fp32 ----------------
__global__ void k_final(const float* __restrict__ W3rel,
                        const float* __restrict__ W3root,
                        const float* __restrict__ b3,
                        const float* __restrict__ Wl,
                        const float* __restrict__ bl,
                        float* __restrict__ out)
{
    __shared__ float pa[128], ph[128], t[128];
    int g = blockIdx.x, n = threadIdx.x;
    int cnt = g_gstart[g + 1] - g_gstart[g];
    float bsel = (cnt > 0) ? 1.0f : 0.0f;
    pa[n] = g_pool[g * 2 * D + n];
    ph[n] = g_pool[g * 2 * D + D + n];
    __syncthreads();
    float acc = b3[n] * bsel;
#pragma unroll 8
    for (int k = 0; k < 128; k++)
        acc += pa[k] * W3rel[k * D + n] + ph[k] * W3root[k * D + n];
    t[n] = acc;
    __syncthreads();
    if (n < DOUT) {
        float o = bl[n];
#pragma unroll 8
        for (int k = 0; k < 128; k++)
            o += t[k] * Wl[k * DOUT + n];
        out[g * DOUT + n] = o;
    }
}

// ---------------- launcher ----------------
extern "C" void kernel_launch(void* const* d_in, const int* in_sizes, int n_in,
                              void* d_out, int out_size) {
    const float* x      = (const float*)d_in[0];
    const int*   ei     = (const int*)d_in[1];
    const int*   batch  = (const int*)d_in[2];
    const float* W1rel  = (const float*)d_in[3];
    const float* b1     = (const float*)d_in[4];
    const float* W1root = (const float*)d_in[5];
    const float* W2rel  = (const float*)d_in[6];
    const float* b2     = (const float*)d_in[7];
    const float* W2root = (const float*)d_in[8];
    const float* W3rel  = (const float*)d_in[9];
    const float* b3     = (const float*)d_in[10];
    const float* W3root = (const float*)d_in[11];
    const float* Wl     = (const float*)d_in[12];
    const float* bl     = (const float*)d_in[13];
    float*       out    = (float*)d_out;

    float *h1, *h2, *agg;
    cudaGetSymbolAddress((void**)&h1, g_h1);
    cudaGetSymbolAddress((void**)&h2, g_h2);
    cudaGetSymbolAddress((void**)&agg, g_agg);

    const int TB = 256;
    int gbN   = (NN + TB - 1) / TB;
    int gbE   = (NE + TB - 1) / TB;
    int gbW   = (NN * 32 + TB - 1) / TB;
    int gbM   = (NN + 127) / 128;
    int gbC   = (NN * D / 4 + TB - 1) / TB;

    k_init<<<gbN, TB>>>();
    k_xcast<<<gbC, TB>>>(x);
    k_hist<<<gbE, TB>>>(ei);
    k_scan<<<1, 1024>>>();
    k_fill<<<gbE, TB>>>(ei);
    k_gbounds<<<1, NG + 1>>>(batch);

    // layer 1: agg over x (fp16 shadow), gemm writes h1 + fp16 shadow of h1
    k_agg<<<gbW, TB>>>();
    k_gemm<<<gbM, TB>>>(agg, x, W1rel, W1root, b1, h1, 1, 1);
    // layer 2: agg over h1 shadow, gemm writes h2 + fp16 shadow of h2
    k_agg<<<gbW, TB>>>();
    k_gemm<<<gbM, TB>>>(agg, h1, W2rel, W2root, b2, h2, 1, 1);
    // layer 3: aggregation only (GEMM folded into pooled head)
    k_agg<<<gbW, TB>>>();
    k_pool<<<NG, 128>>>();
    k_final<<<NG, 128>>>(W3rel, W3root, b3, Wl, bl, out);
}

// round 8
// speedup vs baseline: 1.4679x; 1.4679x over previous
#include <cuda_runtime.h>
#include <cstdint>

#define NN 100000
#define NE 1600000
#define NG 256
#define D  128
#define DOUT 64

// ---------------- scratch (static device globals; no allocs) ----------------
// NOTE: zero-initialized at module load; every kernel_launch leaves g_count
// zeroed again (k_scanC), so the pipeline is replay-deterministic.
__device__ __align__(16) float g_h1[(size_t)NN * D];
__device__ __align__(16) float g_h2[(size_t)NN * D];
__device__ __align__(16) float g_agg[(size_t)NN * D];
__device__ __align__(16) int   g_rowoff[NN + 1];
__device__ __align__(16) int   g_cursor[NN];
__device__ __align__(16) int   g_count[NN];
__device__ __align__(16) int   g_csr[NE];
__device__ __align__(16) float g_deginv[NN];
__device__ __align__(16) float g_pool[NG * 2 * D];
__device__ __align__(16) int   g_gstart[NG + 1];
__device__ __align__(16) int   g_bsum[128];

#define SCAN_BLOCKS 98   // 98 * 1024 >= NN

// ---------------- in-degree histogram over dst ----------------
__global__ void k_hist(const int* __restrict__ ei) {
    int e = blockIdx.x * blockDim.x + threadIdx.x;
    if (e < NE) {
        int d = ei[NE + e];
        atomicAdd(&g_count[d], 1);
    }
}

// ---------------- scan phase A: block-local exclusive scan ----------------
__global__ __launch_bounds__(1024) void k_scanA() {
    __shared__ int sc[1024];
    int t = threadIdx.x;
    int idx = blockIdx.x * 1024 + t;
    int v = (idx < NN) ? g_count[idx] : 0;
    sc[t] = v;
    __syncthreads();
    for (int off = 1; off < 1024; off <<= 1) {
        int u = (t >= off) ? sc[t - off] : 0;
        __syncthreads();
        sc[t] += u;
        __syncthreads();
    }
    if (t == 1023) g_bsum[blockIdx.x] = sc[1023];
    if (idx < NN) g_rowoff[idx] = sc[t] - v;   // local exclusive prefix
}

// ---------------- scan phase B + graph boundaries (one block) ----------------
// threads [0,128): exclusive scan of 98 block sums
// threads [128,385): binary-search graph starts in sorted batch
__global__ __launch_bounds__(512) void k_scanBG(const int* __restrict__ batch) {
    __shared__ int sc[128];
    int t = threadIdx.x;
    if (t < 128) {
        int v = (t < SCAN_BLOCKS) ? g_bsum[t] : 0;
        sc[t] = v;
        __syncthreads();
        for (int off = 1; off < 128; off <<= 1) {
            int u = (t >= off) ? sc[t - off] : 0;
            __syncthreads();
            sc[t] += u;
            __syncthreads();
        }
        if (t < SCAN_BLOCKS) g_bsum[t] = sc[t] - ((t < SCAN_BLOCKS) ? ((t < 128) ? 0 : 0) : 0) - ((t < SCAN_BLOCKS) ? (sc[t] - (sc[t] - ((t == 0) ? sc[0] : sc[t] - sc[t - 1]))) : 0);
    } else {
        // keep non-scan threads clear of the scan's __syncthreads? No:
        // __syncthreads must be block-uniform; handled below.
        __syncthreads();
        for (int off = 1; off < 128; off <<= 1) { __syncthreads(); __syncthreads(); }
    }
    // NOTE: the expression above is wrong-prone; recompute exclusive simply:
    __syncthreads();
    if (t < SCAN_BLOCKS) {
        int incl = sc[t];
        int v;
        v = (t == 0) ? incl : incl - sc[t - 1];
        g_bsum[t] = incl - v;
    }
    // graph boundaries
    int g = t - 128;
    if (g >= 0 && g <= NG) {
        int lo = 0, hi = NN;
        while (lo < hi) {
            int mid = (lo + hi) >> 1;
            if (batch[mid] < g) lo = mid + 1; else hi = mid;
        }
        g_gstart[g] = lo;
    }
}

// ---------------- scan phase C: global offsets + deginv + count re-zero -----
__global__ void k_scanC() {
    int idx = blockIdx.x * blockDim.x + threadIdx.x;
    if (idx < NN) {
        int off = g_rowoff[idx] + g_bsum[idx >> 10];
        g_rowoff[idx] = off;
        g_cursor[idx] = off;
        g_deginv[idx] = 1.0f / (float)max(g_count[idx], 1);
        g_count[idx] = 0;                 // ready for next launch (replay-safe)
    }
    if (idx == 0) g_rowoff[NN] = NE;      // total degree == edge count
}

// ---------------- CSR fill ----------------
__global__ void k_fill(const int* __restrict__ ei) {
    int e = blockIdx.x * blockDim.x + threadIdx.x;
    if (e < NE) {
        int s = ei[e];
        int d = ei[NE + e];
        int pos = atomicAdd(&g_cursor[d], 1);
        g_csr[pos] = s;
    }
}

// ---------------- gather-mean aggregation: one warp per node ----------------
__global__ void k_agg(const float* __restrict__ hin) {
    int node = (blockIdx.x * blockDim.x + threadIdx.x) >> 5;
    if (node >= NN) return;
    int lane = threadIdx.x & 31;
    int beg = g_rowoff[node], end = g_rowoff[node + 1];
    float4 acc = make_float4(0.f, 0.f, 0.f, 0.f);
    for (int e = beg; e < end; e++) {
        int s = g_csr[e];
        float4 v = *(const float4*)(hin + (size_t)s * D + lane * 4);
        acc.x += v.x; acc.y += v.y; acc.z += v.z; acc.w += v.w;
    }
    float sc = g_deginv[node];
    acc.x *= sc; acc.y *= sc; acc.z *= sc; acc.w *= sc;
    *(float4*)(g_agg + (size_t)node * D + lane * 4) = acc;
}

// ---------------- tf32 round-to-nearest helper ----------------
__device__ __forceinline__ float tf32r(float x) {
    uint32_t u;
    asm("cvt.rna.tf32.f32 %0, %1;" : "=r"(u) : "f"(x));
    return __uint_as_float(u);
}

// ---------------- fused GEMM (tf32 tensor cores) ----------------
// hout = act(agg@Wrel + hin@Wroot + b); 128x128 block tile, K=256, BK=16.
__global__ __launch_bounds__(256) void k_gemm(
    const float* __restrict__ A0,
    const float* __restrict__ A1,
    const float* __restrict__ Wrel,
    const float* __restrict__ Wroot,
    const float* __restrict__ bias,
    float* __restrict__ hout,
    int doRelu)
{
    __shared__ float As[16][132];
    __shared__ float Bs[16][132];
    int row0 = blockIdx.x * 128;
    int tid  = threadIdx.x;
    int warp = tid >> 5, lane = tid & 31;
    int wm = warp >> 2;
    int wn = warp & 3;
    int r  = lane >> 2;
    int cq = lane & 3;

    float acc[4][4][4];
#pragma unroll
    for (int mi = 0; mi < 4; mi++)
#pragma unroll
        for (int ni = 0; ni < 4; ni++)
#pragma unroll
            for (int q = 0; q < 4; q++) acc[mi][ni][q] = 0.f;

#pragma unroll 1
    for (int kt = 0; kt < 16; kt++) {
        int k0 = kt * 16;
        const float* src = (k0 < 128) ? A0 : A1;
        const float* W   = (k0 < 128) ? Wrel : Wroot;
        int kc = k0 & 127;

#pragma unroll
        for (int i = 0; i < 2; i++) {
            int slot = tid * 2 + i;
            int rr = slot >> 2;
            int c4 = (slot & 3) * 4;
            float4 v = make_float4(0.f, 0.f, 0.f, 0.f);
            int grow = row0 + rr;
            if (grow < NN)
                v = *(const float4*)(src + (size_t)grow * D + kc + c4);
            As[c4 + 0][rr] = tf32r(v.x);
            As[c4 + 1][rr] = tf32r(v.y);
            As[c4 + 2][rr] = tf32r(v.z);
            As[c4 + 3][rr] = tf32r(v.w);
        }
#pragma unroll
        for (int i = 0; i < 2; i++) {
            int slot = tid * 2 + i;
            int kk = slot >> 5;
            int n4 = (slot & 31) * 4;
            float4 v = *(const float4*)(W + (size_t)(kc + kk) * D + n4);
            float4 cv = make_float4(tf32r(v.x), tf32r(v.y), tf32r(v.z), tf32r(v.w));
            *(float4*)(&Bs[kk][n4]) = cv;
        }
        __syncthreads();

#pragma unroll
        for (int ks = 0; ks < 16; ks += 8) {
            uint32_t bf[4][2];
#pragma unroll
            for (int ni = 0; ni < 4; ni++) {
                int n = wn * 32 + ni * 8 + r;
                bf[ni][0] = __float_as_uint(Bs[ks + cq][n]);
                bf[ni][1] = __float_as_uint(Bs[ks + cq + 4][n]);
            }
#pragma unroll
            for (int mi = 0; mi < 4; mi++) {
                int row = wm * 64 + mi * 16 + r;
                uint32_t a0 = __float_as_uint(As[ks + cq][row]);
                uint32_t a1 = __float_as_uint(As[ks + cq][row + 8]);
                uint32_t a2 = __float_as_uint(As[ks + cq + 4][row]);
                uint32_t a3 = __float_as_uint(As[ks + cq + 4][row + 8]);
#pragma unroll
                for (int ni = 0; ni < 4; ni++) {
                    asm volatile(
                        "mma.sync.aligned.m16n8k8.row.col.f32.tf32.tf32.f32 "
                        "{%0,%1,%2,%3}, {%4,%5,%6,%7}, {%8,%9}, {%0,%1,%2,%3};"
                        : "+f"(acc[mi][ni][0]), "+f"(acc[mi][ni][1]),
                          "+f"(acc[mi][ni][2]), "+f"(acc[mi][ni][3])
                        : "r"(a0), "r"(a1), "r"(a2), "r"(a3),
                          "r"(bf[ni][0]), "r"(bf[ni][1]));
                }
            }
        }
        __syncthreads();
    }

#pragma unroll
    for (int mi = 0; mi < 4; mi++) {
        int r0g = row0 + wm * 64 + mi * 16 + r;
        int r1g = r0g + 8;
#pragma unroll
        for (int ni = 0; ni < 4; ni++) {
            int col = wn * 32 + ni * 8 + 2 * cq;
            float bz0 = bias[col], bz1 = bias[col + 1];
            float v0 = acc[mi][ni][0] + bz0, v1 = acc[mi][ni][1] + bz1;
            float v2 = acc[mi][ni][2] + bz0, v3 = acc[mi][ni][3] + bz1;
            if (doRelu) {
                v0 = fmaxf(v0, 0.f); v1 = fmaxf(v1, 0.f);
                v2 = fmaxf(v2, 0.f); v3 = fmaxf(v3, 0.f);
            }
            if (r0g < NN) *(float2*)(hout + (size_t)r0g * D + col) = make_float2(v0, v1);
            if (r1g < NN) *(float2*)(hout + (size_t)r1g * D + col) = make_float2(v2, v3);
        }
    }
}

// ---------------- pooling: one block per graph over contiguous range ----
__global__ __launch_bounds__(128) void k_pool() {
    int g = blockIdx.x;
    int n = threadIdx.x;
    int beg = g_gstart[g], end = g_gstart[g + 1];
    float sa = 0.f, sh = 0.f;
    for (int node = beg; node < end; node++) {
        sa += g_agg[(size_t)node * D + n];
        sh += g_h2[(size_t)node * D + n];
    }
    int cnt = end - beg;
    float cinv = 1.0f / (float)max(cnt, 1);
    g_pool[g * 2 * D + n]     = sa * cinv;
    g_pool[g * 2 * D + D + n] = sh * cinv;
}

// ---------------- final head: layer3 (pooled) + linear, fp32 ----------------
__global__ void k_final(const float* __restrict__ W3rel,
                        const float* __restrict__ W3root,
                        const float* __restrict__ b3,
                        const float* __restrict__ Wl,
                        const float* __restrict__ bl,
                        float* __restrict__ out)
{
    __shared__ float pa[128], ph[128], t[128];
    int g = blockIdx.x, n = threadIdx.x;
    int cnt = g_gstart[g + 1] - g_gstart[g];
    float bsel = (cnt > 0) ? 1.0f : 0.0f;
    pa[n] = g_pool[g * 2 * D + n];
    ph[n] = g_pool[g * 2 * D + D + n];
    __syncthreads();
    float acc = b3[n] * bsel;
#pragma unroll 8
    for (int k = 0; k < 128; k++)
        acc += pa[k] * W3rel[k * D + n] + ph[k] * W3root[k * D + n];
    t[n] = acc;
    __syncthreads();
    if (n < DOUT) {
        float o = bl[n];
#pragma unroll 8
        for (int k = 0; k < 128; k++)
            o += t[k] * Wl[k * DOUT + n];
        out[g * DOUT + n] = o;
    }
}

// ---------------- launcher ----------------
extern "C" void kernel_launch(void* const* d_in, const int* in_sizes, int n_in,
                              void* d_out, int out_size) {
    const float* x      = (const float*)d_in[0];
    const int*   ei     = (const int*)d_in[1];
    const int*   batch  = (const int*)d_in[2];
    const float* W1rel  = (const float*)d_in[3];
    const float* b1     = (const float*)d_in[4];
    const float* W1root = (const float*)d_in[5];
    const float* W2rel  = (const float*)d_in[6];
    const float* b2     = (const float*)d_in[7];
    const float* W2root = (const float*)d_in[8];
    const float* W3rel  = (const float*)d_in[9];
    const float* b3     = (const float*)d_in[10];
    const float* W3root = (const float*)d_in[11];
    const float* Wl     = (const float*)d_in[12];
    const float* bl     = (const float*)d_in[13];
    float*       out    = (float*)d_out;

    float *h1, *h2, *agg;
    cudaGetSymbolAddress((void**)&h1, g_h1);
    cudaGetSymbolAddress((void**)&h2, g_h2);
    cudaGetSymbolAddress((void**)&agg, g_agg);

    const int TB = 256;
    int gbN   = (NN + TB - 1) / TB;
    int gbE   = (NE + TB - 1) / TB;
    int gbW   = (NN * 32 + TB - 1) / TB;
    int gbM   = (NN + 127) / 128;

    k_hist<<<gbE, TB>>>(ei);
    k_scanA<<<SCAN_BLOCKS, 1024>>>();
    k_scanBG<<<1, 512>>>(batch);
    k_scanC<<<gbN, TB>>>();
    k_fill<<<gbE, TB>>>(ei);

    k_agg<<<gbW, TB>>>(x);
    k_gemm<<<gbM, TB>>>(agg, x, W1rel, W1root, b1, h1, 1);
    k_agg<<<gbW, TB>>>(h1);
    k_gemm<<<gbM, TB>>>(agg, h1, W2rel, W2root, b2, h2, 1);
    k_agg<<<gbW, TB>>>(h2);
    k_pool<<<NG, 128>>>();
    k_final<<<NG, 128>>>(W3rel, W3root, b3, Wl, bl, out);
}

// round 10
// speedup vs baseline: 1.7903x; 1.2196x over previous
#include <cuda_runtime.h>
#include <cstdint>

#define NN 100000
#define NE 1600000
#define NG 256
#define D  128
#define DOUT 64

#define SA 36                 // A smem row stride (words): conflict-free
#define SB 136                // B smem row stride (words): conflict-free
#define AST (128 * SA)
#define BST (32 * SB)
#define GEMM_SMEM ((2 * AST + 2 * BST) * 4)   // 71680 bytes

// ---------------- scratch (static device globals; no allocs) ----------------
__device__ __align__(16) float g_h1[(size_t)NN * D];
__device__ __align__(16) float g_h2[(size_t)NN * D];
__device__ __align__(16) float g_agg[(size_t)NN * D];
__device__ __align__(16) float g_xr[(size_t)NN * D];    // tf32-rounded x
__device__ __align__(16) float g_wr[4 * D * D];         // tf32-rounded W1rel,W1root,W2rel,W2root
__device__ __align__(16) int   g_rowoff[NN + 1];
__device__ __align__(16) int   g_cursor[NN];
__device__ __align__(16) int   g_count[NN];
__device__ __align__(16) int   g_csr[NE];
__device__ __align__(16) float g_deginv[NN];
__device__ __align__(16) float g_pool[NG * 2 * D];
__device__ __align__(16) int   g_gstart[NG + 1];
__device__ __align__(16) int   g_bsum[128];

#define SCAN_BLOCKS 98   // 98 * 1024 >= NN

// ---------------- tf32 round-to-nearest helper ----------------
__device__ __forceinline__ float tf32r(float x) {
    uint32_t u;
    asm("cvt.rna.tf32.f32 %0, %1;" : "=r"(u) : "f"(x));
    return __uint_as_float(u);
}

// ---------------- in-degree histogram over dst ----------------
__global__ void k_hist(const int* __restrict__ ei) {
    int e = blockIdx.x * blockDim.x + threadIdx.x;
    if (e < NE) {
        int d = ei[NE + e];
        atomicAdd(&g_count[d], 1);
    }
}

// ---------------- round x into g_xr (tf32) ----------------
__global__ void k_xround(const float* __restrict__ x) {
    int i = blockIdx.x * blockDim.x + threadIdx.x;
    if (i >= NN * D / 4) return;
    float4 v = *(const float4*)(x + (size_t)i * 4);
    v.x = tf32r(v.x); v.y = tf32r(v.y); v.z = tf32r(v.z); v.w = tf32r(v.w);
    *(float4*)(g_xr + (size_t)i * 4) = v;
}

// ---------------- round the 4 weight matrices into g_wr ----------------
__global__ void k_wround(const float* __restrict__ W1rel, const float* __restrict__ W1root,
                         const float* __restrict__ W2rel, const float* __restrict__ W2root) {
    int i = blockIdx.x * blockDim.x + threadIdx.x;   // 0 .. 4*D*D/4-1 (float4 units)
    if (i >= 4 * D * D / 4) return;
    int m = i / (D * D / 4);
    int o = i % (D * D / 4);
    const float* src = (m == 0) ? W1rel : (m == 1) ? W1root : (m == 2) ? W2rel : W2root;
    float4 v = *(const float4*)(src + (size_t)o * 4);
    v.x = tf32r(v.x); v.y = tf32r(v.y); v.z = tf32r(v.z); v.w = tf32r(v.w);
    *(float4*)(g_wr + (size_t)m * D * D + (size_t)o * 4) = v;
}

// ---------------- scan phase A ----------------
__global__ __launch_bounds__(1024) void k_scanA() {
    __shared__ int sc[1024];
    int t = threadIdx.x;
    int idx = blockIdx.x * 1024 + t;
    int v = (idx < NN) ? g_count[idx] : 0;
    sc[t] = v;
    __syncthreads();
    for (int off = 1; off < 1024; off <<= 1) {
        int u = (t >= off) ? sc[t - off] : 0;
        __syncthreads();
        sc[t] += u;
        __syncthreads();
    }
    if (t == 1023) g_bsum[blockIdx.x] = sc[1023];
    if (idx < NN) g_rowoff[idx] = sc[t] - v;
}

// ---------------- scan phase B + graph boundaries ----------------
__global__ __launch_bounds__(512) void k_scanBG(const int* __restrict__ batch) {
    __shared__ int sc[128];
    int t = threadIdx.x;
    int v = 0;
    if (t < 128) {
        v = (t < SCAN_BLOCKS) ? g_bsum[t] : 0;
        sc[t] = v;
    }
    __syncthreads();
    for (int off = 1; off < 128; off <<= 1) {
        int u = (t < 128 && t >= off) ? sc[t - off] : 0;
        __syncthreads();
        if (t < 128) sc[t] += u;
        __syncthreads();
    }
    if (t < SCAN_BLOCKS) g_bsum[t] = sc[t] - v;
    int g = t - 128;
    if (g >= 0 && g <= NG) {
        int lo = 0, hi = NN;
        while (lo < hi) {
            int mid = (lo + hi) >> 1;
            if (batch[mid] < g) lo = mid + 1; else hi = mid;
        }
        g_gstart[g] = lo;
    }
}

// ---------------- scan phase C ----------------
__global__ void k_scanC() {
    int idx = blockIdx.x * blockDim.x + threadIdx.x;
    if (idx < NN) {
        int off = g_rowoff[idx] + g_bsum[idx >> 10];
        g_rowoff[idx] = off;
        g_cursor[idx] = off;
        g_deginv[idx] = 1.0f / (float)max(g_count[idx], 1);
        g_count[idx] = 0;
    }
    if (idx == 0) g_rowoff[NN] = NE;
}

// ---------------- CSR fill ----------------
__global__ void k_fill(const int* __restrict__ ei) {
    int e = blockIdx.x * blockDim.x + threadIdx.x;
    if (e < NE) {
        int s = ei[e];
        int d = ei[NE + e];
        int pos = atomicAdd(&g_cursor[d], 1);
        g_csr[pos] = s;
    }
}

// ---------------- gather-mean aggregation (optional tf32 rounding) ---------
__global__ void k_agg(const float* __restrict__ hin, int roundOut) {
    int node = (blockIdx.x * blockDim.x + threadIdx.x) >> 5;
    if (node >= NN) return;
    int lane = threadIdx.x & 31;
    int beg = g_rowoff[node], end = g_rowoff[node + 1];
    float4 acc = make_float4(0.f, 0.f, 0.f, 0.f);
    for (int e = beg; e < end; e++) {
        int s = g_csr[e];
        float4 v = *(const float4*)(hin + (size_t)s * D + lane * 4);
        acc.x += v.x; acc.y += v.y; acc.z += v.z; acc.w += v.w;
    }
    float sc = g_deginv[node];
    acc.x *= sc; acc.y *= sc; acc.z *= sc; acc.w *= sc;
    if (roundOut) {
        acc.x = tf32r(acc.x); acc.y = tf32r(acc.y);
        acc.z = tf32r(acc.z); acc.w = tf32r(acc.w);
    }
    *(float4*)(g_agg + (size_t)node * D + lane * 4) = acc;
}

// ---------------- cp.async helpers ----------------
__device__ __forceinline__ void cpa16(uint32_t dst, const void* src, uint32_t srcsize) {
    asm volatile("cp.async.cg.shared.global [%0], [%1], 16, %2;"
                 :: "r"(dst), "l"(src), "r"(srcsize) : "memory");
}
__device__ __forceinline__ uint32_t smem_u32(const void* p) {
    uint32_t a;
    asm("{ .reg .u64 t; cvta.to.shared.u64 t, %1; cvt.u32.u64 %0, t; }" : "=r"(a) : "l"(p));
    return a;
}

// ---------------- fused GEMM (tf32 mma, cp.async double-buffered) ----------
// Inputs are PRE-ROUNDED to tf32. roundHout: store hout tf32-rounded.
__global__ __launch_bounds__(256) void k_gemm(
    const float* __restrict__ A0,
    const float* __restrict__ A1,
    const float* __restrict__ Wrel,
    const float* __restrict__ Wroot,
    const float* __restrict__ bias,
    float* __restrict__ hout,
    int doRelu, int roundHout)
{
    extern __shared__ float sm[];
    int row0 = blockIdx.x * 128;
    int tid  = threadIdx.x;
    int warp = tid >> 5, lane = tid & 31;
    int wm = warp >> 2;
    int wn = warp & 3;
    int r  = lane >> 2;
    int cq = lane & 3;
    uint32_t smbase = smem_u32(sm);

    float acc[4][4][4];
#pragma unroll
    for (int mi = 0; mi < 4; mi++)
#pragma unroll
        for (int ni = 0; ni < 4; ni++)
#pragma unroll
            for (int q = 0; q < 4; q++) acc[mi][ni][q] = 0.f;

    auto load_stage = [&](int s, int kt) {
        const float* srcA = (kt < 4) ? A0 : A1;
        const float* W    = (kt < 4) ? Wrel : Wroot;
        int kc = (kt * 32) & 127;
        uint32_t aBase = smbase + (uint32_t)(s * AST) * 4;
        uint32_t bBase = smbase + (uint32_t)(2 * AST + s * BST) * 4;
#pragma unroll
        for (int i = 0; i < 4; i++) {
            int c = tid + i * 256;
            int row = c >> 3, kch = c & 7;
            int grow = row0 + row;
            int ok = (grow < NN);
            const float* p = srcA + (size_t)(ok ? grow : 0) * D + kc + kch * 4;
            cpa16(aBase + (uint32_t)(row * SA + kch * 4) * 4, p, ok ? 16u : 0u);
        }
#pragma unroll
        for (int i = 0; i < 4; i++) {
            int c = tid + i * 256;
            int kr = c >> 5, n4 = c & 31;
            const float* p = W + (size_t)(kc + kr) * D + n4 * 4;
            cpa16(bBase + (uint32_t)(kr * SB + n4 * 4) * 4, p, 16u);
        }
        asm volatile("cp.async.commit_group;" ::: "memory");
    };

    load_stage(0, 0);
    load_stage(1, 1);

#pragma unroll 1
    for (int kt = 0; kt < 8; kt++) {
        if (kt < 7) asm volatile("cp.async.wait_group 1;" ::: "memory");
        else        asm volatile("cp.async.wait_group 0;" ::: "memory");
        __syncthreads();

        int s = kt & 1;
        const float* as = sm + s * AST;
        const float* bs = sm + 2 * AST + s * BST;
#pragma unroll
        for (int ks = 0; ks < 32; ks += 8) {
            uint32_t bf[4][2];
#pragma unroll
            for (int ni = 0; ni < 4; ni++) {
                int n = wn * 32 + ni * 8 + r;
                bf[ni][0] = __float_as_uint(bs[(ks + cq) * SB + n]);
                bf[ni][1] = __float_as_uint(bs[(ks + cq + 4) * SB + n]);
            }
#pragma unroll
            for (int mi = 0; mi < 4; mi++) {
                int row = wm * 64 + mi * 16 + r;
                uint32_t a0 = __float_as_uint(as[row * SA + ks + cq]);
                uint32_t a1 = __float_as_uint(as[(row + 8) * SA + ks + cq]);
                uint32_t a2 = __float_as_uint(as[row * SA + ks + cq + 4]);
                uint32_t a3 = __float_as_uint(as[(row + 8) * SA + ks + cq + 4]);
#pragma unroll
                for (int ni = 0; ni < 4; ni++) {
                    asm volatile(
                        "mma.sync.aligned.m16n8k8.row.col.f32.tf32.tf32.f32 "
                        "{%0,%1,%2,%3}, {%4,%5,%6,%7}, {%8,%9}, {%0,%1,%2,%3};"
                        : "+f"(acc[mi][ni][0]), "+f"(acc[mi][ni][1]),
                          "+f"(acc[mi][ni][2]), "+f"(acc[mi][ni][3])
                        : "r"(a0), "r"(a1), "r"(a2), "r"(a3),
                          "r"(bf[ni][0]), "r"(bf[ni][1]));
                }
            }
        }
        __syncthreads();
        if (kt + 2 < 8) load_stage(s, kt + 2);
    }

#pragma unroll
    for (int mi = 0; mi < 4; mi++) {
        int r0g = row0 + wm * 64 + mi * 16 + r;
        int r1g = r0g + 8;
#pragma unroll
        for (int ni = 0; ni < 4; ni++) {
            int col = wn * 32 + ni * 8 + 2 * cq;
            float bz0 = bias[col], bz1 = bias[col + 1];
            float v0 = acc[mi][ni][0] + bz0, v1 = acc[mi][ni][1] + bz1;
            float v2 = acc[mi][ni][2] + bz0, v3 = acc[mi][ni][3] + bz1;
            if (doRelu) {
                v0 = fmaxf(v0, 0.f); v1 = fmaxf(v1, 0.f);
                v2 = fmaxf(v2, 0.f); v3 = fmaxf(v3, 0.f);
            }
            if (roundHout) {
                v0 = tf32r(v0); v1 = tf32r(v1);
                v2 = tf32r(v2); v3 = tf32r(v3);
            }
            if (r0g < NN) *(float2*)(hout + (size_t)r0g * D + col) = make_float2(v0, v1);
            if (r1g < NN) *(float2*)(hout + (size_t)r1g * D + col) = make_float2(v2, v3);
        }
    }
}

// ---------------- pooling ----------------
__global__ __launch_bounds__(128) void k_pool() {
    int g = blockIdx.x;
    int n = threadIdx.x;
    int beg = g_gstart[g], end = g_gstart[g + 1];
    float sa = 0.f, sh = 0.f;
    for (int node = beg; node < end; node++) {
        sa += g_agg[(size_t)node * D + n];
        sh += g_h2[(size_t)node * D + n];
    }
    int cnt = end - beg;
    float cinv = 1.0f / (float)max(cnt, 1);
    g_pool[g * 2 * D + n]     = sa * cinv;
    g_pool[g * 2 * D + D + n] = sh * cinv;
}

// ---------------- final head ----------------
__global__ void k_final(const float* __restrict__ W3rel,
                        const float* __restrict__ W3root,
                        const float* __restrict__ b3,
                        const float* __restrict__ Wl,
                        const float* __restrict__ bl,
                        float* __restrict__ out)
{
    __shared__ float pa[128], ph[128], t[128];
    int g = blockIdx.x, n = threadIdx.x;
    int cnt = g_gstart[g + 1] - g_gstart[g];
    float bsel = (cnt > 0) ? 1.0f : 0.0f;
    pa[n] = g_pool[g * 2 * D + n];
    ph[n] = g_pool[g * 2 * D + D + n];
    __syncthreads();
    float acc = b3[n] * bsel;
#pragma unroll 8
    for (int k = 0; k < 128; k++)
        acc += pa[k] * W3rel[k * D + n] + ph[k] * W3root[k * D + n];
    t[n] = acc;
    __syncthreads();
    if (n < DOUT) {
        float o = bl[n];
#pragma unroll 8
        for (int k = 0; k < 128; k++)
            o += t[k] * Wl[k * DOUT + n];
        out[g * DOUT + n] = o;
    }
}

// ---------------- launcher ----------------
extern "C" void kernel_launch(void* const* d_in, const int* in_sizes, int n_in,
                              void* d_out, int out_size) {
    const float* x      = (const float*)d_in[0];
    const int*   ei     = (const int*)d_in[1];
    const int*   batch  = (const int*)d_in[2];
    const float* W1rel  = (const float*)d_in[3];
    const float* b1     = (const float*)d_in[4];
    const float* W1root = (const float*)d_in[5];
    const float* W2rel  = (const float*)d_in[6];
    const float* b2     = (const float*)d_in[7];
    const float* W2root = (const float*)d_in[8];
    const float* W3rel  = (const float*)d_in[9];
    const float* b3     = (const float*)d_in[10];
    const float* W3root = (const float*)d_in[11];
    const float* Wl     = (const float*)d_in[12];
    const float* bl     = (const float*)d_in[13];
    float*       out    = (float*)d_out;

    float *h1, *h2, *agg, *xr, *wr;
    cudaGetSymbolAddress((void**)&h1, g_h1);
    cudaGetSymbolAddress((void**)&h2, g_h2);
    cudaGetSymbolAddress((void**)&agg, g_agg);
    cudaGetSymbolAddress((void**)&xr, g_xr);
    cudaGetSymbolAddress((void**)&wr, g_wr);

    static int smem_set = 0;
    if (!smem_set) {
        cudaFuncSetAttribute(k_gemm, cudaFuncAttributeMaxDynamicSharedMemorySize, GEMM_SMEM);
        smem_set = 1;
    }

    const int TB = 256;
    int gbN = (NN + TB - 1) / TB;
    int gbE = (NE + TB - 1) / TB;
    int gbW = (NN * 32 + TB - 1) / TB;
    int gbM = (NN + 127) / 128;
    int gbX = (NN * D / 4 + TB - 1) / TB;
    int gbWr = (4 * D * D / 4 + TB - 1) / TB;

    k_hist<<<gbE, TB>>>(ei);
    k_xround<<<gbX, TB>>>(x);
    k_wround<<<gbWr, TB>>>(W1rel, W1root, W2rel, W2root);
    k_scanA<<<SCAN_BLOCKS, 1024>>>();
    k_scanBG<<<1, 512>>>(batch);
    k_scanC<<<gbN, TB>>>();
    k_fill<<<gbE, TB>>>(ei);

    // layer 1: agg(x) rounded, gemm with rounded inputs, h1 stored rounded
    k_agg<<<gbW, TB>>>(x, 1);
    k_gemm<<<gbM, TB, GEMM_SMEM>>>(agg, xr, wr, wr + D * D, b1, h1, 1, 1);
    // layer 2: agg(h1) rounded, h2 stored full fp32 (pooling path)
    k_agg<<<gbW, TB>>>(h1, 1);
    k_gemm<<<gbM, TB, GEMM_SMEM>>>(agg, h1, wr + 2 * D * D, wr + 3 * D * D, b2, h2, 1, 0);
    // layer 3: fp32 agg only
    k_agg<<<gbW, TB>>>(h2, 0);
    k_pool<<<NG, 128>>>();
    k_final<<<NG, 128>>>(W3rel, W3root, b3, Wl, bl, out);
}